// round 1
// baseline (speedup 1.0000x reference)
#include <cuda_runtime.h>
#include <math.h>

#define BB 64
#define TT 2048
#define FF 64
#define HH 160
#define GG 480            // 3*H
#define BT (BB*TT)        // 131072
#define WPAD 481          // odd pad -> conflict-free transposed weight smem

// ---------------- scratch (device globals; allocation-free) ----------------
__device__ float g_z  [BT*FF];          //  32 MB
__device__ float g_xg1[BT*GG];          // 252 MB
__device__ float g_h1 [BT*HH];          //  84 MB
__device__ float g_xg2[BT*GG];          // 252 MB
__device__ float g_h2T[BB*HH];

// ============================================================================
// K1: dilated conv (k=3, dil=2, pad=2) + batchnorm(inference) + exact GELU
//     x[B,T,F] -> g_z[B,T,F]
// ============================================================================
#define K1_TT 32
__global__ void k1_conv(const float* __restrict__ x, const float* __restrict__ mix_w,
                        const float* __restrict__ bn_g, const float* __restrict__ bn_b,
                        const float* __restrict__ bn_m, const float* __restrict__ bn_v)
{
    extern __shared__ float sm[];
    float* ws = sm;                    // [3][64][64] : ws[(k*64+i)*64+f]
    float* xs = sm + 3*64*64;          // [36][64]    : rows t0-2 .. t0+33
    const int b  = blockIdx.y;
    const int t0 = blockIdx.x * K1_TT;
    const int tid = threadIdx.x;       // 256 threads

    for (int idx = tid; idx < FF*FF*3; idx += 256) {
        int f = idx / 192; int rem = idx - f*192; int i = rem / 3; int k = rem - i*3;
        ws[(k*64 + i)*64 + f] = mix_w[idx];
    }
    for (int idx = tid; idx < 36*64; idx += 256) {
        int r = idx >> 6; int i = idx & 63;
        int t = t0 - 2 + r;
        xs[idx] = (t >= 0 && t < TT) ? x[((b*TT) + t)*64 + i] : 0.f;
    }
    __syncthreads();

    const int f  = tid & 63;
    const int tg = tid >> 6;           // 0..3
    const float sc = bn_g[f] * rsqrtf(bn_v[f] + 1e-5f);
    const float sh = bn_b[f] - bn_m[f] * sc;
    const float4* xs4 = (const float4*)xs;

    for (int m = 0; m < 8; m++) {
        int tl = tg + 4*m;             // 0..31
        float acc = 0.f;
        #pragma unroll
        for (int k = 0; k < 3; k++) {
            int r = tl + 2*k;
            const float* wk = ws + k*4096 + f;
            #pragma unroll
            for (int i4 = 0; i4 < 16; i4++) {
                float4 xv = xs4[r*16 + i4];
                acc += xv.x * wk[(i4*4 + 0)*64];
                acc += xv.y * wk[(i4*4 + 1)*64];
                acc += xv.z * wk[(i4*4 + 2)*64];
                acc += xv.w * wk[(i4*4 + 3)*64];
            }
        }
        float y  = acc * sc + sh;
        float zz = 0.5f * y * (1.f + erff(y * 0.70710678118654752f));
        g_z[((b*TT) + (t0 + tl))*64 + f] = zz;
    }
}
#define SMEM1 ((3*64*64 + 36*64)*4)

// ============================================================================
// K2: xg1 = g_z @ w_ih1^T + b_ih1      [BT,64] @ [64,480]
//     persistent grid=148; thread owns col c, 64 weights in regs
// ============================================================================
__global__ __launch_bounds__(480) void k2_xproj(const float* __restrict__ w_ih,
                                                const float* __restrict__ b_ih)
{
    extern __shared__ float sm[];
    float* wT = sm;                    // [64][WPAD]
    float* zs = sm + 64*WPAD;          // [64][64]
    const int c = threadIdx.x;

    for (int idx = c; idx < GG*FF; idx += 480) {
        int cc = idx >> 6; int k = idx & 63;
        wT[k*WPAD + cc] = w_ih[idx];
    }
    __syncthreads();
    float wreg[64];
    #pragma unroll
    for (int k = 0; k < 64; k++) wreg[k] = wT[k*WPAD + c];
    const float bias = b_ih[c];

    const int start = blockIdx.x * 896;          // 14 tiles of 64 rows
    for (int tile = 0; tile < 14; tile++) {
        int r0 = start + tile*64;
        if (r0 >= BT) break;
        __syncthreads();
        for (int idx = c; idx < 64*64; idx += 480) {
            int r = idx >> 6; int i = idx & 63;
            zs[idx] = g_z[(r0 + r)*64 + i];
        }
        __syncthreads();
        const float4* zs4 = (const float4*)zs;
        for (int r = 0; r < 64; r++) {
            float acc = bias;
            #pragma unroll
            for (int i4 = 0; i4 < 16; i4++) {
                float4 zv = zs4[r*16 + i4];
                acc += zv.x*wreg[i4*4+0] + zv.y*wreg[i4*4+1]
                     + zv.z*wreg[i4*4+2] + zv.w*wreg[i4*4+3];
            }
            g_xg1[(r0 + r)*GG + c] = acc;
        }
    }
}
#define SMEM2 ((64*WPAD + 64*64)*4)

// ============================================================================
// K4: xg2 = g_h1 @ w_ih2^T + b_ih2     [BT,160] @ [160,480]
//     hybrid weights: k<80 regs, k>=80 smem transposed. 2-row micro-tile.
// ============================================================================
__global__ __launch_bounds__(480) void k4_xproj160(const float* __restrict__ w_ih,
                                                   const float* __restrict__ b_ih)
{
    extern __shared__ float sm[];
    float* wT = sm;                    // [80][WPAD]
    float* zs = sm + 80*WPAD;          // [16][160]
    const int c = threadIdx.x;

    // phase 1: stage k<80 transposed, pull into regs
    for (int idx = c; idx < GG*HH; idx += 480) {
        int cc = idx / 160; int k = idx - cc*160;
        if (k < 80) wT[k*WPAD + cc] = w_ih[idx];
    }
    __syncthreads();
    float wreg[80];
    #pragma unroll
    for (int k = 0; k < 80; k++) wreg[k] = wT[k*WPAD + c];
    const float bias = b_ih[c];
    __syncthreads();
    // phase 2: stage k>=80 (stays in smem for the hot loop)
    for (int idx = c; idx < GG*HH; idx += 480) {
        int cc = idx / 160; int k = idx - cc*160;
        if (k >= 80) wT[(k - 80)*WPAD + cc] = w_ih[idx];
    }
    __syncthreads();

    const int start = blockIdx.x * 896;          // 56 tiles of 16 rows
    for (int tile = 0; tile < 56; tile++) {
        int r0 = start + tile*16;
        if (r0 >= BT) break;
        for (int idx = c; idx < 16*160; idx += 480) {
            int r = idx / 160; int i = idx - r*160;
            zs[idx] = g_h1[(r0 + r)*160 + i];
        }
        __syncthreads();
        const float4* zs4 = (const float4*)zs;
        for (int rg = 0; rg < 16; rg += 2) {
            float a0 = bias, a1 = bias;
            #pragma unroll
            for (int q = 0; q < 20; q++) {       // reg half
                float4 h0 = zs4[(rg+0)*40 + q];
                float4 h1 = zs4[(rg+1)*40 + q];
                float w0 = wreg[4*q+0], w1 = wreg[4*q+1], w2 = wreg[4*q+2], w3 = wreg[4*q+3];
                a0 += h0.x*w0 + h0.y*w1 + h0.z*w2 + h0.w*w3;
                a1 += h1.x*w0 + h1.y*w1 + h1.z*w2 + h1.w*w3;
            }
            #pragma unroll
            for (int q = 0; q < 20; q++) {       // smem half
                float4 h0 = zs4[(rg+0)*40 + 20 + q];
                float4 h1 = zs4[(rg+1)*40 + 20 + q];
                float w0 = wT[(4*q+0)*WPAD + c];
                float w1 = wT[(4*q+1)*WPAD + c];
                float w2 = wT[(4*q+2)*WPAD + c];
                float w3 = wT[(4*q+3)*WPAD + c];
                a0 += h0.x*w0 + h0.y*w1 + h0.z*w2 + h0.w*w3;
                a1 += h1.x*w0 + h1.y*w1 + h1.z*w2 + h1.w*w3;
            }
            g_xg2[(r0 + rg + 0)*GG + c] = a0;
            g_xg2[(r0 + rg + 1)*GG + c] = a1;
        }
        __syncthreads();
    }
}
#define SMEM4 ((80*WPAD + 16*160)*4)

// ============================================================================
// K3: GRU recurrence. 1 CTA per batch element, 480 threads (thread g = gate row).
//     Hybrid weights: k<80 regs, k>=80 smem transposed [k][g].
//     which=0: xg=g_xg1, store all h into g_h1.  which=1: xg=g_xg2, final only.
// ============================================================================
__global__ __launch_bounds__(480) void k_gru(const float* __restrict__ w_hh,
                                             const float* __restrict__ b_hh,
                                             int which)
{
    extern __shared__ float sm[];
    float* wT = sm;                          // [80][WPAD]
    __shared__ __align__(16) float h_s[160];
    __shared__ float hp[480];
    __shared__ float xsm[480];
    const int g = threadIdx.x;
    const int b = blockIdx.x;

    const float* __restrict__ xg = which ? g_xg2 : g_xg1;

    // stage k<80 transposed -> regs
    for (int idx = g; idx < GG*HH; idx += 480) {
        int cc = idx / 160; int k = idx - cc*160;
        if (k < 80) wT[k*WPAD + cc] = w_hh[idx];
    }
    __syncthreads();
    float wreg[80];
    #pragma unroll
    for (int k = 0; k < 80; k++) wreg[k] = wT[k*WPAD + g];
    const float bias = b_hh[g];
    __syncthreads();
    // stage k>=80 (hot-loop smem)
    for (int idx = g; idx < GG*HH; idx += 480) {
        int cc = idx / 160; int k = idx - cc*160;
        if (k >= 80) wT[(k - 80)*WPAD + cc] = w_hh[idx];
    }
    if (g < 160) h_s[g] = 0.f;
    __syncthreads();

    const float4* h4 = (const float4*)h_s;
    const float* xgb = xg + (size_t)b * TT * GG;

    for (int t = 0; t < TT; t++) {
        float xv  = xgb[t*GG + g];
        float acc = bias;
        #pragma unroll
        for (int q = 0; q < 20; q++) {           // reg half (k<80)
            float4 hv = h4[q];
            acc += hv.x*wreg[4*q+0] + hv.y*wreg[4*q+1]
                 + hv.z*wreg[4*q+2] + hv.w*wreg[4*q+3];
        }
        #pragma unroll
        for (int q = 0; q < 20; q++) {           // smem half (k>=80)
            float4 hv = h4[20 + q];
            float w0 = wT[(4*q+0)*WPAD + g];
            float w1 = wT[(4*q+1)*WPAD + g];
            float w2 = wT[(4*q+2)*WPAD + g];
            float w3 = wT[(4*q+3)*WPAD + g];
            acc += hv.x*w0 + hv.y*w1 + hv.z*w2 + hv.w*w3;
        }
        hp[g]  = acc;       // h-part + b_hh (needed raw for n-gate)
        xsm[g] = xv;        // x-part (incl. b_ih)
        __syncthreads();
        if (g < 160) {
            float r = 1.f / (1.f + expf(-(xsm[g]       + hp[g])));
            float u = 1.f / (1.f + expf(-(xsm[160 + g] + hp[160 + g])));
            float n = tanhf(xsm[320 + g] + r * hp[320 + g]);
            float hn = (1.f - u)*n + u*h_s[g];
            h_s[g] = hn;
            if (!which) g_h1[(size_t)(b*TT + t)*HH + g] = hn;
        }
        __syncthreads();
    }
    if (g < 160 && which) g_h2T[b*HH + g] = h_s[g];
}
#define SMEMG (80*WPAD*4)

// ============================================================================
// K5: head.  q = gelu(h2T @ hw1^T + hb1); out = q @ hw2^T + hb2
// ============================================================================
__global__ void k_head(const float* __restrict__ hw1, const float* __restrict__ hb1,
                       const float* __restrict__ hw2, const float* __restrict__ hb2,
                       float* __restrict__ out)
{
    __shared__ float q[80];
    const int b = blockIdx.x;
    const int j = threadIdx.x;       // 128 threads, 80 active
    const float* h = g_h2T + b*HH;
    if (j < 80) {
        float acc = hb1[j];
        #pragma unroll 4
        for (int k = 0; k < 160; k++) acc += h[k] * hw1[j*160 + k];
        q[j] = 0.5f * acc * (1.f + erff(acc * 0.70710678118654752f));
    }
    __syncthreads();
    if (j < 2) {
        float o = hb2[j];
        #pragma unroll 4
        for (int k = 0; k < 80; k++) o += q[k] * hw2[j*80 + k];
        out[b*2 + j] = o;
    }
}

// ============================================================================
extern "C" void kernel_launch(void* const* d_in, const int* in_sizes, int n_in,
                              void* d_out, int out_size)
{
    const float* x     = (const float*)d_in[0];
    const float* mix_w = (const float*)d_in[1];
    const float* bn_g  = (const float*)d_in[2];
    const float* bn_b  = (const float*)d_in[3];
    const float* bn_m  = (const float*)d_in[4];
    const float* bn_v  = (const float*)d_in[5];
    const float* w_ih1 = (const float*)d_in[6];
    const float* w_hh1 = (const float*)d_in[7];
    const float* b_ih1 = (const float*)d_in[8];
    const float* b_hh1 = (const float*)d_in[9];
    const float* w_ih2 = (const float*)d_in[10];
    const float* w_hh2 = (const float*)d_in[11];
    const float* b_ih2 = (const float*)d_in[12];
    const float* b_hh2 = (const float*)d_in[13];
    const float* hw1   = (const float*)d_in[14];
    const float* hb1   = (const float*)d_in[15];
    const float* hw2   = (const float*)d_in[16];
    const float* hb2   = (const float*)d_in[17];
    float* out = (float*)d_out;

    cudaFuncSetAttribute(k1_conv,     cudaFuncAttributeMaxDynamicSharedMemorySize, SMEM1);
    cudaFuncSetAttribute(k2_xproj,    cudaFuncAttributeMaxDynamicSharedMemorySize, SMEM2);
    cudaFuncSetAttribute(k4_xproj160, cudaFuncAttributeMaxDynamicSharedMemorySize, SMEM4);
    cudaFuncSetAttribute(k_gru,       cudaFuncAttributeMaxDynamicSharedMemorySize, SMEMG);

    k1_conv<<<dim3(TT/K1_TT, BB), 256, SMEM1>>>(x, mix_w, bn_g, bn_b, bn_m, bn_v);
    k2_xproj<<<148, 480, SMEM2>>>(w_ih1, b_ih1);
    k_gru<<<BB, 480, SMEMG>>>(w_hh1, b_hh1, 0);
    k4_xproj160<<<148, 480, SMEM4>>>(w_ih2, b_ih2);
    k_gru<<<BB, 480, SMEMG>>>(w_hh2, b_hh2, 1);
    k_head<<<BB, 128>>>(hw1, hb1, hw2, hb2, out);
}

// round 5
// speedup vs baseline: 1.0301x; 1.0301x over previous
#include <cuda_runtime.h>
#include <stdint.h>
#include <math.h>

#define BB 64
#define TT 2048
#define FF 64
#define HH 160
#define GG 480            // 3*H
#define BT (BB*TT)        // 131072

typedef unsigned long long ull;
typedef unsigned int u32;

// ---------------- scratch (device globals; allocation-free) ----------------
__device__ float g_z  [BT*FF];
__device__ float g_xg1[BT*GG];
__device__ float g_h1 [BT*HH];
__device__ float g_xg2[BT*GG];
__device__ float g_h2T[BB*HH];

// ---------------- packed f32x2 helpers ----------------
__device__ __forceinline__ ull fma2(ull a, ull b, ull c) {
    ull d;
    asm("fma.rn.f32x2 %0, %1, %2, %3;" : "=l"(d) : "l"(a), "l"(b), "l"(c));
    return d;
}
__device__ __forceinline__ float f2sum(ull u) {
    float x, y;
    asm("mov.b64 {%0,%1}, %2;" : "=f"(x), "=f"(y) : "l"(u));
    return x + y;
}
__device__ __forceinline__ ull fpack(float lo, float hi) {
    ull p;
    asm("mov.b64 %0, {%1,%2};" : "=l"(p) : "f"(lo), "f"(hi));
    return p;
}

__device__ __forceinline__ float fsig(float x) {
    return __fdividef(1.f, 1.f + __expf(-x));
}
__device__ __forceinline__ float ftanh(float x) {
    return __fdividef(2.f, 1.f + __expf(-2.f * x)) - 1.f;
}

// ============================================================================
// K1: dilated conv (k=3, dil=2, pad=2) + batchnorm(inference) + exact GELU
// ============================================================================
#define K1_TT 32
__global__ void k1_conv(const float* __restrict__ x, const float* __restrict__ mix_w,
                        const float* __restrict__ bn_g, const float* __restrict__ bn_b,
                        const float* __restrict__ bn_m, const float* __restrict__ bn_v)
{
    extern __shared__ float sm[];
    float* ws = sm;                    // [3][64][64] : ws[(k*64+i)*64+f]
    float* xs = sm + 3*64*64;          // [36][64]
    const int b  = blockIdx.y;
    const int t0 = blockIdx.x * K1_TT;
    const int tid = threadIdx.x;       // 256 threads

    for (int idx = tid; idx < FF*FF*3; idx += 256) {
        int f = idx / 192; int rem = idx - f*192; int i = rem / 3; int k = rem - i*3;
        ws[(k*64 + i)*64 + f] = mix_w[idx];
    }
    for (int idx = tid; idx < 36*64; idx += 256) {
        int r = idx >> 6; int i = idx & 63;
        int t = t0 - 2 + r;
        xs[idx] = (t >= 0 && t < TT) ? x[((b*TT) + t)*64 + i] : 0.f;
    }
    __syncthreads();

    const int f  = tid & 63;
    const int tg = tid >> 6;
    const float sc = bn_g[f] * rsqrtf(bn_v[f] + 1e-5f);
    const float sh = bn_b[f] - bn_m[f] * sc;
    const float4* xs4 = (const float4*)xs;

    for (int m = 0; m < 8; m++) {
        int tl = tg + 4*m;
        float acc = 0.f;
        #pragma unroll
        for (int k = 0; k < 3; k++) {
            int r = tl + 2*k;
            const float* wk = ws + k*4096 + f;
            #pragma unroll
            for (int i4 = 0; i4 < 16; i4++) {
                float4 xv = xs4[r*16 + i4];
                acc += xv.x * wk[(i4*4 + 0)*64];
                acc += xv.y * wk[(i4*4 + 1)*64];
                acc += xv.z * wk[(i4*4 + 2)*64];
                acc += xv.w * wk[(i4*4 + 3)*64];
            }
        }
        float y  = acc * sc + sh;
        float zz = 0.5f * y * (1.f + erff(y * 0.70710678118654752f));
        g_z[((b*TT) + (t0 + tl))*64 + f] = zz;
    }
}
#define SMEM1 ((3*64*64 + 36*64)*4)

// ============================================================================
// K2: xg1 = g_z @ w_ih1^T + b_ih1      [BT,64] @ [64,480]  — all-reg, f32x2
// ============================================================================
__global__ __launch_bounds__(480) void k2_xproj(const float* __restrict__ w_ih,
                                                const float* __restrict__ b_ih)
{
    extern __shared__ float zs[];      // [64][64]
    const int c = threadIdx.x;

    ull wr[32];
    #pragma unroll
    for (int i = 0; i < 16; i++) {
        ulonglong2 v = *reinterpret_cast<const ulonglong2*>(w_ih + c*64 + 4*i);
        wr[2*i] = v.x; wr[2*i+1] = v.y;
    }
    const float bias = b_ih[c];

    const int start = blockIdx.x * 896;          // 14 tiles of 64 rows
    for (int tile = 0; tile < 14; tile++) {
        int r0 = start + tile*64;
        if (r0 >= BT) break;
        __syncthreads();
        for (int idx = c; idx < 64*16; idx += 480)
            ((float4*)zs)[idx] = ((const float4*)(g_z + (size_t)r0*64))[idx];
        __syncthreads();
        for (int r = 0; r < 64; r += 2) {
            ull a0 = 0ull, a1 = 0ull, b0 = 0ull, b1 = 0ull;
            const float* z0 = zs + r*64;
            const float* z1 = zs + r*64 + 64;
            #pragma unroll
            for (int i = 0; i < 16; i++) {
                ulonglong2 h0 = *reinterpret_cast<const ulonglong2*>(z0 + 4*i);
                ulonglong2 h1 = *reinterpret_cast<const ulonglong2*>(z1 + 4*i);
                a0 = fma2(h0.x, wr[2*i],   a0);
                a1 = fma2(h0.y, wr[2*i+1], a1);
                b0 = fma2(h1.x, wr[2*i],   b0);
                b1 = fma2(h1.y, wr[2*i+1], b1);
            }
            g_xg1[(size_t)(r0 + r    )*GG + c] = bias + f2sum(a0) + f2sum(a1);
            g_xg1[(size_t)(r0 + r + 1)*GG + c] = bias + f2sum(b0) + f2sum(b1);
        }
    }
}
#define SMEM2 (64*64*4)

// ============================================================================
// K4: xg2 = g_h1 @ w_ih2^T + b_ih2     [BT,160] @ [160,480]
//     hybrid: k<80 in regs (f32x2), k>=80 in smem as ull pairs [q][480+1]
//     4-row micro-tile
// ============================================================================
#define K4_WS 481
__global__ __launch_bounds__(480) void k4_xproj160(const float* __restrict__ w_ih,
                                                   const float* __restrict__ b_ih)
{
    extern __shared__ __align__(16) char smraw[];
    ull*   wsm = (ull*)smraw;                      // [40][481] k-pairs for k>=80
    float* zs  = (float*)(smraw + 40*K4_WS*8);     // [16][160]
    const int c = threadIdx.x;

    // stage smem half: pair (80+2q, 81+2q) for column cc
    for (int idx = c; idx < 480*40; idx += 480) {
        int cc = idx / 40; int q = idx - cc*40;
        float lo = w_ih[cc*160 + 80 + 2*q];
        float hi = w_ih[cc*160 + 81 + 2*q];
        wsm[q*K4_WS + cc] = fpack(lo, hi);
    }
    // reg half k<80
    ull wr[40];
    #pragma unroll
    for (int i = 0; i < 20; i++) {
        ulonglong2 v = *reinterpret_cast<const ulonglong2*>(w_ih + c*160 + 4*i);
        wr[2*i] = v.x; wr[2*i+1] = v.y;
    }
    const float bias = b_ih[c];

    const int start = blockIdx.x * 896;            // 56 tiles of 16 rows
    for (int tile = 0; tile < 56; tile++) {
        int r0 = start + tile*16;
        if (r0 >= BT) break;
        __syncthreads();
        for (int idx = c; idx < 16*40; idx += 480)
            ((float4*)zs)[idx] = ((const float4*)(g_h1 + (size_t)r0*160))[idx];
        __syncthreads();
        for (int rg = 0; rg < 16; rg += 4) {
            const float* z0 = zs + (rg+0)*160;
            const float* z1 = zs + (rg+1)*160;
            const float* z2 = zs + (rg+2)*160;
            const float* z3 = zs + (rg+3)*160;
            ull a0 = 0ull, a1 = 0ull, a2 = 0ull, a3 = 0ull;
            #pragma unroll
            for (int i = 0; i < 20; i++) {          // reg half, k = 4i..4i+3
                ull wa = wr[2*i], wb = wr[2*i+1];
                ulonglong2 h;
                h = *reinterpret_cast<const ulonglong2*>(z0 + 4*i);
                a0 = fma2(h.x, wa, a0); a0 = fma2(h.y, wb, a0);
                h = *reinterpret_cast<const ulonglong2*>(z1 + 4*i);
                a1 = fma2(h.x, wa, a1); a1 = fma2(h.y, wb, a1);
                h = *reinterpret_cast<const ulonglong2*>(z2 + 4*i);
                a2 = fma2(h.x, wa, a2); a2 = fma2(h.y, wb, a2);
                h = *reinterpret_cast<const ulonglong2*>(z3 + 4*i);
                a3 = fma2(h.x, wa, a3); a3 = fma2(h.y, wb, a3);
            }
            #pragma unroll
            for (int i = 0; i < 20; i++) {          // smem half, k = 80+4i..83+4i
                ull wa = wsm[(2*i  )*K4_WS + c];
                ull wb = wsm[(2*i+1)*K4_WS + c];
                ulonglong2 h;
                h = *reinterpret_cast<const ulonglong2*>(z0 + 80 + 4*i);
                a0 = fma2(h.x, wa, a0); a0 = fma2(h.y, wb, a0);
                h = *reinterpret_cast<const ulonglong2*>(z1 + 80 + 4*i);
                a1 = fma2(h.x, wa, a1); a1 = fma2(h.y, wb, a1);
                h = *reinterpret_cast<const ulonglong2*>(z2 + 80 + 4*i);
                a2 = fma2(h.x, wa, a2); a2 = fma2(h.y, wb, a2);
                h = *reinterpret_cast<const ulonglong2*>(z3 + 80 + 4*i);
                a3 = fma2(h.x, wa, a3); a3 = fma2(h.y, wb, a3);
            }
            g_xg2[(size_t)(r0 + rg    )*GG + c] = bias + f2sum(a0);
            g_xg2[(size_t)(r0 + rg + 1)*GG + c] = bias + f2sum(a1);
            g_xg2[(size_t)(r0 + rg + 2)*GG + c] = bias + f2sum(a2);
            g_xg2[(size_t)(r0 + rg + 3)*GG + c] = bias + f2sum(a3);
        }
    }
}
#define SMEM4 (40*K4_WS*8 + 16*160*4)

// ============================================================================
// K3: GRU recurrence, cluster of 2 CTAs per batch element.
//     rank owns hidden units [rank*80, rank*80+80) -> 240 gate rows/CTA.
//     2 threads per row (k-split 80/80), ALL weights in registers (f32x2).
//     h double-buffered in smem; peer half pushed via st.shared::cluster;
//     one barrier.cluster per step.
// ============================================================================
__global__ __launch_bounds__(480) void k_gru(const float* __restrict__ w_hh,
                                             const float* __restrict__ b_hh,
                                             int which)
{
    __shared__ __align__(16) float h_s[2][HH];
    __shared__ float hp[240];

    const int tid  = threadIdx.x;
    const int b    = blockIdx.x >> 1;
    u32 rank;
    asm("mov.u32 %0, %%cluster_ctarank;" : "=r"(rank));
    const int h0   = rank * 80;
    const int row  = tid >> 1;          // 0..239
    const int half = tid & 1;

    // global gate row: row<80 -> r-gate, <160 -> z, <240 -> n  (unit h0+j)
    const int gt = row / 80;
    const int j  = row - gt*80;
    const int G  = gt*160 + h0 + j;

    // weights -> registers
    ull wr[40];
    #pragma unroll
    for (int i = 0; i < 20; i++) {
        ulonglong2 v = *reinterpret_cast<const ulonglong2*>(w_hh + G*160 + 80*half + 4*i);
        wr[2*i] = v.x; wr[2*i+1] = v.y;
    }
    const float bias = b_hh[G];

    // remote smem base for peer's h_s
    u32 ls = (u32)__cvta_generic_to_shared(&h_s[0][0]);
    u32 rs;
    asm("mapa.shared::cluster.u32 %0, %1, %2;" : "=r"(rs) : "r"(ls), "r"(rank ^ 1u));

    if (tid < HH) h_s[0][tid] = 0.f;
    __syncthreads();

    const float* __restrict__ xgb = (which ? g_xg2 : g_xg1) + (size_t)b * TT * GG;

    // prefetch xg for t=0 (update threads only)
    float xr = 0.f, xz = 0.f, xn = 0.f;
    if (tid < 80) {
        xr = xgb[      h0 + tid];
        xz = xgb[160 + h0 + tid];
        xn = xgb[320 + h0 + tid];
    }

    for (int t = 0; t < TT; t++) {
        const int buf = t & 1;
        const float* hb = &h_s[buf][80*half];

        ull a0 = 0ull, a1 = 0ull;
        #pragma unroll
        for (int i = 0; i < 20; i++) {
            ulonglong2 hv = *reinterpret_cast<const ulonglong2*>(hb + 4*i);
            a0 = fma2(hv.x, wr[2*i],   a0);
            a1 = fma2(hv.y, wr[2*i+1], a1);
        }
        float p = f2sum(a0) + f2sum(a1);
        float full = p + __shfl_xor_sync(0xffffffffu, p, 1);
        if (!half) hp[row] = full + bias;
        __syncthreads();

        if (tid < 80) {
            const int i = tid;
            float cxr = xr, cxz = xz, cxn = xn;
            if (t + 1 < TT) {                       // prefetch next step
                const float* nx = xgb + (size_t)(t+1)*GG;
                xr = nx[      h0 + i];
                xz = nx[160 + h0 + i];
                xn = nx[320 + h0 + i];
            }
            float r  = fsig(cxr + hp[i]);
            float u  = fsig(cxz + hp[80 + i]);
            float n  = ftanh(cxn + r * hp[160 + i]);
            float hn = (1.f - u) * n + u * h_s[buf][h0 + i];

            int nb = buf ^ 1;
            h_s[nb][h0 + i] = hn;                                   // local
            u32 ra = rs + (u32)(nb*HH + h0 + i) * 4u;               // peer
            asm volatile("st.shared::cluster.f32 [%0], %1;" :: "r"(ra), "f"(hn) : "memory");
            if (!which) g_h1[(size_t)(b*TT + t)*HH + h0 + i] = hn;
        }

        asm volatile("barrier.cluster.arrive.aligned;" ::: "memory");
        asm volatile("barrier.cluster.wait.aligned;"   ::: "memory");
    }

    if (which && tid < 80)
        g_h2T[b*HH + h0 + tid] = h_s[0][h0 + tid];   // TT even -> final in buf 0
}

// ============================================================================
// K5: head
// ============================================================================
__global__ void k_head(const float* __restrict__ hw1, const float* __restrict__ hb1,
                       const float* __restrict__ hw2, const float* __restrict__ hb2,
                       float* __restrict__ out)
{
    __shared__ float q[80];
    const int b = blockIdx.x;
    const int j = threadIdx.x;
    const float* h = g_h2T + b*HH;
    if (j < 80) {
        float acc = hb1[j];
        #pragma unroll 4
        for (int k = 0; k < 160; k++) acc += h[k] * hw1[j*160 + k];
        q[j] = 0.5f * acc * (1.f + erff(acc * 0.70710678118654752f));
    }
    __syncthreads();
    if (j < 2) {
        float o = hb2[j];
        #pragma unroll 4
        for (int k = 0; k < 80; k++) o += q[k] * hw2[j*80 + k];
        out[b*2 + j] = o;
    }
}

// ============================================================================
static void launch_gru(const float* w_hh, const float* b_hh, int which)
{
    cudaLaunchConfig_t cfg = {};
    cfg.gridDim  = dim3(2*BB, 1, 1);
    cfg.blockDim = dim3(480, 1, 1);
    cfg.dynamicSmemBytes = 0;
    cfg.stream = 0;
    cudaLaunchAttribute attrs[1];
    attrs[0].id = cudaLaunchAttributeClusterDimension;
    attrs[0].val.clusterDim.x = 2;
    attrs[0].val.clusterDim.y = 1;
    attrs[0].val.clusterDim.z = 1;
    cfg.attrs = attrs;
    cfg.numAttrs = 1;
    cudaLaunchKernelEx(&cfg, k_gru, w_hh, b_hh, which);
}

extern "C" void kernel_launch(void* const* d_in, const int* in_sizes, int n_in,
                              void* d_out, int out_size)
{
    const float* x     = (const float*)d_in[0];
    const float* mix_w = (const float*)d_in[1];
    const float* bn_g  = (const float*)d_in[2];
    const float* bn_b  = (const float*)d_in[3];
    const float* bn_m  = (const float*)d_in[4];
    const float* bn_v  = (const float*)d_in[5];
    const float* w_ih1 = (const float*)d_in[6];
    const float* w_hh1 = (const float*)d_in[7];
    const float* b_ih1 = (const float*)d_in[8];
    const float* b_hh1 = (const float*)d_in[9];
    const float* w_ih2 = (const float*)d_in[10];
    const float* w_hh2 = (const float*)d_in[11];
    const float* b_ih2 = (const float*)d_in[12];
    const float* b_hh2 = (const float*)d_in[13];
    const float* hw1   = (const float*)d_in[14];
    const float* hb1   = (const float*)d_in[15];
    const float* hw2   = (const float*)d_in[16];
    const float* hb2   = (const float*)d_in[17];
    float* out = (float*)d_out;

    cudaFuncSetAttribute(k1_conv,     cudaFuncAttributeMaxDynamicSharedMemorySize, SMEM1);
    cudaFuncSetAttribute(k2_xproj,    cudaFuncAttributeMaxDynamicSharedMemorySize, SMEM2);
    cudaFuncSetAttribute(k4_xproj160, cudaFuncAttributeMaxDynamicSharedMemorySize, SMEM4);

    k1_conv<<<dim3(TT/K1_TT, BB), 256, SMEM1>>>(x, mix_w, bn_g, bn_b, bn_m, bn_v);
    k2_xproj<<<148, 480, SMEM2>>>(w_ih1, b_ih1);
    launch_gru(w_hh1, b_hh1, 0);
    k4_xproj160<<<148, 480, SMEM4>>>(w_ih2, b_ih2);
    launch_gru(w_hh2, b_hh2, 1);
    k_head<<<BB, 128>>>(hw1, hb1, hw2, hb2, out);
}